// round 3
// baseline (speedup 1.0000x reference)
#include <cuda_runtime.h>
#include <cuda_bf16.h>
#include <cstddef>

// Problem constants (fixed by the reference setup_inputs)
#define NN 50000
#define HD 128
#define NE 640000

// Scratch (device globals — no allocation allowed)
__device__ float g_agg[(size_t)NN * HD];
__device__ float g_h1[(size_t)NN * HD];
__device__ float g_invdeg[NN];
__device__ int   g_deg[NN];
__device__ int   g_e64;   // 1 if edge buffer is int64, 0 if int32

// ---------------------------------------------------------------------------
// Edge dtype detection: if edge is int64 (values < 2^31), every odd int32
// word is 0. If int32, odd words hold random node ids (nonzero w.h.p.).
// ---------------------------------------------------------------------------
__global__ void k_detect(const int* __restrict__ e32) {
    if (blockIdx.x == 0 && threadIdx.x == 0) {
        int is64 = 1;
        for (int i = 1; i < 512; i += 2)
            if (e32[i] != 0) { is64 = 0; break; }
        g_e64 = is64;
    }
}

__device__ __forceinline__ int edge_src(const int* __restrict__ e32, int e, int is64) {
    return is64 ? e32[2 * (size_t)e] : e32[e];
}
__device__ __forceinline__ int edge_dst(const int* __restrict__ e32, int e, int is64) {
    return is64 ? e32[2 * ((size_t)NE + e)] : e32[(size_t)NE + e];
}

// ---------------------------------------------------------------------------
// Degree kernels
// ---------------------------------------------------------------------------
__global__ void k_zero_deg() {
    int i = blockIdx.x * blockDim.x + threadIdx.x;
    if (i < NN) g_deg[i] = 0;
}

__global__ void k_count(const int* __restrict__ e32) {
    int e = blockIdx.x * blockDim.x + threadIdx.x;
    if (e < NE) {
        int is64 = g_e64;
        int dst = edge_dst(e32, e, is64);
        if ((unsigned)dst < NN) atomicAdd(&g_deg[dst], 1);
    }
}

__global__ void k_invdeg() {
    int i = blockIdx.x * blockDim.x + threadIdx.x;
    if (i < NN) g_invdeg[i] = 1.0f / fmaxf((float)g_deg[i], 1.0f);
}

// ---------------------------------------------------------------------------
// Zero the aggregation buffer
// ---------------------------------------------------------------------------
__global__ void k_zero_agg() {
    size_t i = (size_t)blockIdx.x * blockDim.x + threadIdx.x;
    size_t n = (size_t)NN * HD / 4;
    float4* p = (float4*)g_agg;
    float4 z = make_float4(0.f, 0.f, 0.f, 0.f);
    for (; i < n; i += (size_t)gridDim.x * blockDim.x) p[i] = z;
}

// ---------------------------------------------------------------------------
// Scatter: agg[dst] += x[src] * att[e]   (one warp per edge, 4 floats/lane)
// x == nullptr -> read from g_h1
// ---------------------------------------------------------------------------
__global__ __launch_bounds__(256) void k_scatter(
    const float* __restrict__ xin, const int* __restrict__ e32,
    const float* __restrict__ att)
{
    const float* x = xin ? xin : g_h1;
    int t = blockIdx.x * blockDim.x + threadIdx.x;
    int e = t >> 5;
    if (e >= NE) return;
    int lane = t & 31;
    int is64 = g_e64;

    int src = edge_src(e32, e, is64);
    int dst = edge_dst(e32, e, is64);
    if ((unsigned)src >= NN || (unsigned)dst >= NN) return;
    float a = att[e];

    float4 v = *(const float4*)(x + (size_t)src * HD + lane * 4);
    float* p = g_agg + (size_t)dst * HD + lane * 4;
    atomicAdd(p + 0, v.x * a);
    atomicAdd(p + 1, v.y * a);
    atomicAdd(p + 2, v.z * a);
    atomicAdd(p + 3, v.w * a);
}

// ---------------------------------------------------------------------------
// Fused: OUT = relu( cat(X, g_agg * inv_deg) @ W + bias )
// M=NN, K=256, N=128.  Tile: BM=128, BN=128, BK=32, 256 threads, 8x8/thread.
// A-tile k-chunks never straddle k=128, so the cat is virtual.
// X == nullptr -> read g_h1;  OUT == nullptr -> write g_h1.
// ---------------------------------------------------------------------------
__global__ __launch_bounds__(256) void k_gemm(
    const float* __restrict__ Xin,   // [NN, 128] first half of cat (or null)
    const float* __restrict__ W,     // [256, 128] row-major
    const float* __restrict__ bias,  // [128]
    float* __restrict__ OUTin)       // [NN, 128] (or null)
{
    const float* X   = Xin   ? Xin   : g_h1;
    float*       OUT = OUTin ? OUTin : g_h1;

    __shared__ __align__(16) float As[32][132];  // [k][m], padded
    __shared__ __align__(16) float Bs[32][128];  // [k][n]

    const int tid  = threadIdx.x;
    const int row0 = blockIdx.x * 128;
    const int tx   = tid & 15;   // output col group
    const int ty   = tid >> 4;   // output row group

    float acc[8][8];
#pragma unroll
    for (int i = 0; i < 8; i++)
#pragma unroll
        for (int j = 0; j < 8; j++) acc[i][j] = 0.f;

    const int a_r  = tid >> 3;        // 0..31
    const int a_c4 = (tid & 7) * 4;   // 0..28
    const int b_r  = tid >> 5;        // 0..7
    const int b_c4 = (tid & 31) * 4;  // 0..124

#pragma unroll 1
    for (int kt = 0; kt < 8; kt++) {
        const int  k0     = kt * 32;
        const bool second = (kt >= 4);
        const float* Abase = second ? g_agg : X;
        const int  kk     = second ? (k0 - 128) : k0;

        // Load A tile (128 rows x 32 cols), applying inv_deg for the agg half
#pragma unroll
        for (int i = 0; i < 4; i++) {
            int r = a_r + i * 32;
            int grow = row0 + r;
            float4 v = make_float4(0.f, 0.f, 0.f, 0.f);
            float s = 1.f;
            if (grow < NN) {
                v = *(const float4*)(Abase + (size_t)grow * HD + kk + a_c4);
                if (second) s = g_invdeg[grow];
            }
            As[a_c4 + 0][r] = v.x * s;
            As[a_c4 + 1][r] = v.y * s;
            As[a_c4 + 2][r] = v.z * s;
            As[a_c4 + 3][r] = v.w * s;
        }
        // Load B tile (32 rows x 128 cols), contiguous
#pragma unroll
        for (int i = 0; i < 4; i++) {
            int r = b_r + i * 8;
            *(float4*)&Bs[r][b_c4] =
                *(const float4*)(W + (size_t)(k0 + r) * HD + b_c4);
        }
        __syncthreads();

#pragma unroll
        for (int k = 0; k < 32; k++) {
            float a[8], b[8];
            *(float4*)&a[0] = *(const float4*)&As[k][ty * 8];
            *(float4*)&a[4] = *(const float4*)&As[k][ty * 8 + 4];
            *(float4*)&b[0] = *(const float4*)&Bs[k][tx * 8];
            *(float4*)&b[4] = *(const float4*)&Bs[k][tx * 8 + 4];
#pragma unroll
            for (int i = 0; i < 8; i++)
#pragma unroll
                for (int j = 0; j < 8; j++)
                    acc[i][j] = fmaf(a[i], b[j], acc[i][j]);
        }
        __syncthreads();
    }

    // Epilogue: bias + relu, float4 stores
    float bv[8];
    *(float4*)&bv[0] = *(const float4*)(bias + tx * 8);
    *(float4*)&bv[4] = *(const float4*)(bias + tx * 8 + 4);
#pragma unroll
    for (int i = 0; i < 8; i++) {
        int grow = row0 + ty * 8 + i;
        if (grow < NN) {
            float4 o0, o1;
            o0.x = fmaxf(acc[i][0] + bv[0], 0.f);
            o0.y = fmaxf(acc[i][1] + bv[1], 0.f);
            o0.z = fmaxf(acc[i][2] + bv[2], 0.f);
            o0.w = fmaxf(acc[i][3] + bv[3], 0.f);
            o1.x = fmaxf(acc[i][4] + bv[4], 0.f);
            o1.y = fmaxf(acc[i][5] + bv[5], 0.f);
            o1.z = fmaxf(acc[i][6] + bv[6], 0.f);
            o1.w = fmaxf(acc[i][7] + bv[7], 0.f);
            *(float4*)(OUT + (size_t)grow * HD + tx * 8)     = o0;
            *(float4*)(OUT + (size_t)grow * HD + tx * 8 + 4) = o1;
        }
    }
}

// ---------------------------------------------------------------------------
// Launch — kernel launches only, no other CUDA API calls.
// ---------------------------------------------------------------------------
extern "C" void kernel_launch(void* const* d_in, const int* in_sizes, int n_in,
                              void* d_out, int out_size) {
    const float* data = (const float*)d_in[0];
    const int*   e32  = (const int*)d_in[1];   // int32 or int64 (detected on device)
    const float* att  = (const float*)d_in[2];
    const float* w1   = (const float*)d_in[3];
    const float* b1   = (const float*)d_in[4];
    const float* w2   = (const float*)d_in[5];
    const float* b2   = (const float*)d_in[6];
    float*       out  = (float*)d_out;

    // Edge dtype detection + degrees (shared by both layers)
    k_detect<<<1, 32>>>(e32);
    k_zero_deg<<<(NN + 255) / 256, 256>>>();
    k_count<<<(NE + 255) / 256, 256>>>(e32);
    k_invdeg<<<(NN + 255) / 256, 256>>>();

    const int scatter_blocks = (NE * 32 + 255) / 256;
    const int gemm_blocks    = (NN + 127) / 128;

    // Layer 1: agg(data) -> h1 = relu(cat(data, agg)@w1 + b1)
    k_zero_agg<<<1600, 256>>>();
    k_scatter<<<scatter_blocks, 256>>>(data, e32, att);
    k_gemm<<<gemm_blocks, 256>>>(data, w1, b1, nullptr);

    // Layer 2: agg(h1) -> out = relu(cat(h1, agg)@w2 + b2)
    k_zero_agg<<<1600, 256>>>();
    k_scatter<<<scatter_blocks, 256>>>(nullptr, e32, att);
    k_gemm<<<gemm_blocks, 256>>>(nullptr, w2, b2, out);
}

// round 4
// speedup vs baseline: 2.1485x; 2.1485x over previous
#include <cuda_runtime.h>
#include <cuda_bf16.h>
#include <cstddef>

// Problem constants (fixed by the reference setup_inputs)
#define NN 50000
#define HD 128
#define NE 640000
#define NB 196   // (NN + 255) / 256

// Scratch (device globals — no allocation allowed)
__device__ float g_agg[(size_t)NN * HD];
__device__ float g_h1[(size_t)NN * HD];
__device__ int   g_deg[NN];
__device__ int   g_cursor[NN];
__device__ int   g_off[NN + 1];
__device__ int   g_part[256];
__device__ int   g_csrc[NE];   // CSR: src node per slot
__device__ float g_catt[NE];   // CSR: att weight per slot
__device__ int   g_e64;        // 1 if edge buffer is int64, 0 if int32

// ---------------------------------------------------------------------------
// Edge dtype detection: if edge is int64 (values < 2^31), every odd int32
// word is 0. If int32, odd words hold random node ids (nonzero w.h.p.).
// ---------------------------------------------------------------------------
__global__ void k_detect(const int* __restrict__ e32) {
    if (blockIdx.x == 0 && threadIdx.x == 0) {
        int is64 = 1;
        for (int i = 1; i < 512; i += 2)
            if (e32[i] != 0) { is64 = 0; break; }
        g_e64 = is64;
    }
}

__device__ __forceinline__ int edge_src(const int* __restrict__ e32, int e, int is64) {
    return is64 ? e32[2 * (size_t)e] : e32[e];
}
__device__ __forceinline__ int edge_dst(const int* __restrict__ e32, int e, int is64) {
    return is64 ? e32[2 * ((size_t)NE + e)] : e32[(size_t)NE + e];
}

// ---------------------------------------------------------------------------
// CSR build
// ---------------------------------------------------------------------------
__global__ void k_zero_counts() {
    int i = blockIdx.x * blockDim.x + threadIdx.x;
    if (i < NN) { g_deg[i] = 0; g_cursor[i] = 0; }
}

__global__ void k_count(const int* __restrict__ e32) {
    int e = blockIdx.x * blockDim.x + threadIdx.x;
    if (e < NE) {
        int dst = edge_dst(e32, e, g_e64);
        if ((unsigned)dst < NN) atomicAdd(&g_deg[dst], 1);
    }
}

// Per-block sums of deg
__global__ void k_scan_block() {
    __shared__ int sh[256];
    int i = blockIdx.x * 256 + threadIdx.x;
    sh[threadIdx.x] = (i < NN) ? g_deg[i] : 0;
    __syncthreads();
#pragma unroll
    for (int s = 128; s > 0; s >>= 1) {
        if (threadIdx.x < s) sh[threadIdx.x] += sh[threadIdx.x + s];
        __syncthreads();
    }
    if (threadIdx.x == 0) g_part[blockIdx.x] = sh[0];
}

// Exclusive scan of NB block sums (single block)
__global__ void k_scan_top() {
    __shared__ int sh[256];
    int t = threadIdx.x;
    sh[t] = (t < NB) ? g_part[t] : 0;
    __syncthreads();
#pragma unroll
    for (int off = 1; off < 256; off <<= 1) {
        int v = (t >= off) ? sh[t - off] : 0;
        __syncthreads();
        sh[t] += v;
        __syncthreads();
    }
    g_part[t] = (t > 0) ? sh[t - 1] : 0;   // exclusive
}

// Per-block local scan + base -> g_off
__global__ void k_scan_down() {
    __shared__ int sh[256];
    int t = threadIdx.x;
    int i = blockIdx.x * 256 + t;
    int d = (i < NN) ? g_deg[i] : 0;
    sh[t] = d;
    __syncthreads();
#pragma unroll
    for (int off = 1; off < 256; off <<= 1) {
        int v = (t >= off) ? sh[t - off] : 0;
        __syncthreads();
        sh[t] += v;
        __syncthreads();
    }
    int excl = g_part[blockIdx.x] + sh[t] - d;
    if (i < NN) g_off[i] = excl;
    if (i == NN - 1) g_off[NN] = excl + d;
}

// Fill CSR slots: (src, att) in destination order
__global__ void k_fill(const int* __restrict__ e32, const float* __restrict__ att) {
    int e = blockIdx.x * blockDim.x + threadIdx.x;
    if (e >= NE) return;
    int is64 = g_e64;
    int src = edge_src(e32, e, is64);
    int dst = edge_dst(e32, e, is64);
    if ((unsigned)src >= NN || (unsigned)dst >= NN) return;
    int pos = atomicAdd(&g_cursor[dst], 1);
    int slot = g_off[dst] + pos;
    g_csrc[slot] = src;
    g_catt[slot] = att[e];
}

// ---------------------------------------------------------------------------
// Gather aggregation: one warp per destination node.
// agg[n] = (1/max(deg,1)) * sum_{edges into n} x[src] * att
// x == nullptr -> read from g_h1. inv_deg folded in.
// ---------------------------------------------------------------------------
__global__ __launch_bounds__(256) void k_gather(const float* __restrict__ xin) {
    const float* x = xin ? xin : g_h1;
    int t = blockIdx.x * blockDim.x + threadIdx.x;
    int n = t >> 5;
    if (n >= NN) return;
    int lane = t & 31;

    int beg = g_off[n];
    int end = g_off[n + 1];

    float4 acc = make_float4(0.f, 0.f, 0.f, 0.f);
    int i = beg;
    for (; i + 1 < end; i += 2) {
        int   s0 = g_csrc[i],     s1 = g_csrc[i + 1];
        float a0 = g_catt[i],     a1 = g_catt[i + 1];
        float4 v0 = *(const float4*)(x + (size_t)s0 * HD + lane * 4);
        float4 v1 = *(const float4*)(x + (size_t)s1 * HD + lane * 4);
        acc.x += v0.x * a0 + v1.x * a1;
        acc.y += v0.y * a0 + v1.y * a1;
        acc.z += v0.z * a0 + v1.z * a1;
        acc.w += v0.w * a0 + v1.w * a1;
    }
    if (i < end) {
        int   s0 = g_csrc[i];
        float a0 = g_catt[i];
        float4 v0 = *(const float4*)(x + (size_t)s0 * HD + lane * 4);
        acc.x += v0.x * a0;
        acc.y += v0.y * a0;
        acc.z += v0.z * a0;
        acc.w += v0.w * a0;
    }

    float inv = 1.f / fmaxf((float)(end - beg), 1.f);
    acc.x *= inv; acc.y *= inv; acc.z *= inv; acc.w *= inv;
    *(float4*)(g_agg + (size_t)n * HD + lane * 4) = acc;
}

// ---------------------------------------------------------------------------
// Fused: OUT = relu( cat(X, g_agg) @ W + bias )   (g_agg already mean-scaled)
// M=NN, K=256, N=128.  Tile: BM=128, BN=128, BK=32, 256 threads, 8x8/thread.
// X == nullptr -> read g_h1;  OUT == nullptr -> write g_h1.
// ---------------------------------------------------------------------------
__global__ __launch_bounds__(256) void k_gemm(
    const float* __restrict__ Xin,   // [NN, 128] first half of cat (or null)
    const float* __restrict__ W,     // [256, 128] row-major
    const float* __restrict__ bias,  // [128]
    float* __restrict__ OUTin)       // [NN, 128] (or null)
{
    const float* X   = Xin   ? Xin   : g_h1;
    float*       OUT = OUTin ? OUTin : g_h1;

    __shared__ __align__(16) float As[32][132];  // [k][m], padded
    __shared__ __align__(16) float Bs[32][128];  // [k][n]

    const int tid  = threadIdx.x;
    const int row0 = blockIdx.x * 128;
    const int tx   = tid & 15;   // output col group
    const int ty   = tid >> 4;   // output row group

    float acc[8][8];
#pragma unroll
    for (int i = 0; i < 8; i++)
#pragma unroll
        for (int j = 0; j < 8; j++) acc[i][j] = 0.f;

    const int a_r  = tid >> 3;        // 0..31
    const int a_c4 = (tid & 7) * 4;   // 0..28
    const int b_r  = tid >> 5;        // 0..7
    const int b_c4 = (tid & 31) * 4;  // 0..124

#pragma unroll 1
    for (int kt = 0; kt < 8; kt++) {
        const int  k0     = kt * 32;
        const bool second = (kt >= 4);
        const float* Abase = second ? g_agg : X;
        const int  kk     = second ? (k0 - 128) : k0;

        // Load A tile (128 rows x 32 cols)
#pragma unroll
        for (int i = 0; i < 4; i++) {
            int r = a_r + i * 32;
            int grow = row0 + r;
            float4 v = make_float4(0.f, 0.f, 0.f, 0.f);
            if (grow < NN)
                v = *(const float4*)(Abase + (size_t)grow * HD + kk + a_c4);
            As[a_c4 + 0][r] = v.x;
            As[a_c4 + 1][r] = v.y;
            As[a_c4 + 2][r] = v.z;
            As[a_c4 + 3][r] = v.w;
        }
        // Load B tile (32 rows x 128 cols), contiguous
#pragma unroll
        for (int i = 0; i < 4; i++) {
            int r = b_r + i * 8;
            *(float4*)&Bs[r][b_c4] =
                *(const float4*)(W + (size_t)(k0 + r) * HD + b_c4);
        }
        __syncthreads();

#pragma unroll
        for (int k = 0; k < 32; k++) {
            float a[8], b[8];
            *(float4*)&a[0] = *(const float4*)&As[k][ty * 8];
            *(float4*)&a[4] = *(const float4*)&As[k][ty * 8 + 4];
            *(float4*)&b[0] = *(const float4*)&Bs[k][tx * 8];
            *(float4*)&b[4] = *(const float4*)&Bs[k][tx * 8 + 4];
#pragma unroll
            for (int i = 0; i < 8; i++)
#pragma unroll
                for (int j = 0; j < 8; j++)
                    acc[i][j] = fmaf(a[i], b[j], acc[i][j]);
        }
        __syncthreads();
    }

    // Epilogue: bias + relu, float4 stores
    float bv[8];
    *(float4*)&bv[0] = *(const float4*)(bias + tx * 8);
    *(float4*)&bv[4] = *(const float4*)(bias + tx * 8 + 4);
#pragma unroll
    for (int i = 0; i < 8; i++) {
        int grow = row0 + ty * 8 + i;
        if (grow < NN) {
            float4 o0, o1;
            o0.x = fmaxf(acc[i][0] + bv[0], 0.f);
            o0.y = fmaxf(acc[i][1] + bv[1], 0.f);
            o0.z = fmaxf(acc[i][2] + bv[2], 0.f);
            o0.w = fmaxf(acc[i][3] + bv[3], 0.f);
            o1.x = fmaxf(acc[i][4] + bv[4], 0.f);
            o1.y = fmaxf(acc[i][5] + bv[5], 0.f);
            o1.z = fmaxf(acc[i][6] + bv[6], 0.f);
            o1.w = fmaxf(acc[i][7] + bv[7], 0.f);
            *(float4*)(OUT + (size_t)grow * HD + tx * 8)     = o0;
            *(float4*)(OUT + (size_t)grow * HD + tx * 8 + 4) = o1;
        }
    }
}

// ---------------------------------------------------------------------------
// Launch — kernel launches only, no other CUDA API calls.
// ---------------------------------------------------------------------------
extern "C" void kernel_launch(void* const* d_in, const int* in_sizes, int n_in,
                              void* d_out, int out_size) {
    const float* data = (const float*)d_in[0];
    const int*   e32  = (const int*)d_in[1];   // int32 or int64 (detected on device)
    const float* att  = (const float*)d_in[2];
    const float* w1   = (const float*)d_in[3];
    const float* b1   = (const float*)d_in[4];
    const float* w2   = (const float*)d_in[5];
    const float* b2   = (const float*)d_in[6];
    float*       out  = (float*)d_out;

    const int eb = (NE + 255) / 256;
    const int gather_blocks = (NN * 32 + 255) / 256;
    const int gemm_blocks   = (NN + 127) / 128;

    // CSR build (shared by both layers)
    k_detect<<<1, 32>>>(e32);
    k_zero_counts<<<NB, 256>>>();
    k_count<<<eb, 256>>>(e32);
    k_scan_block<<<NB, 256>>>();
    k_scan_top<<<1, 256>>>();
    k_scan_down<<<NB, 256>>>();
    k_fill<<<eb, 256>>>(e32, att);

    // Layer 1: agg(data) -> h1 = relu(cat(data, agg)@w1 + b1)
    k_gather<<<gather_blocks, 256>>>(data);
    k_gemm<<<gemm_blocks, 256>>>(data, w1, b1, nullptr);

    // Layer 2: agg(h1) -> out = relu(cat(h1, agg)@w2 + b2)
    k_gather<<<gather_blocks, 256>>>(nullptr);
    k_gemm<<<gemm_blocks, 256>>>(nullptr, w2, b2, out);
}

// round 8
// speedup vs baseline: 3.0548x; 1.4218x over previous
#include <cuda_runtime.h>
#include <cuda_bf16.h>
#include <cstdint>
#include <cstddef>

// Problem constants (fixed by the reference setup_inputs)
#define NN 50000
#define HD 128
#define NE 640000
#define NB 196   // (NN + 255) / 256

// Scratch (device globals — no allocation allowed)
__device__ float g_agg[(size_t)NN * HD];
__device__ float g_h1[(size_t)NN * HD];
__device__ int   g_deg[NN];
__device__ int   g_cursor[NN];
__device__ int   g_off[NN + 1];
__device__ int   g_part[256];
__device__ int   g_csrc[NE];   // CSR: src node per slot
__device__ float g_catt[NE];   // CSR: att weight per slot
__device__ int   g_e64;        // 1 if edge buffer is int64, 0 if int32

// ===========================================================================
// Warp-level MMA helpers (baseline PTX, valid on plain compute_103)
// ===========================================================================
__device__ __forceinline__ uint32_t smem_to_u32(const void* p) {
    uint32_t a;
    asm("{ .reg .u64 t; cvta.to.shared.u64 t, %1; cvt.u32.u64 %0, t; }"
        : "=r"(a) : "l"(p));
    return a;
}
__device__ __forceinline__ void ldsm4(uint32_t* r, uint32_t addr) {
    asm volatile("ldmatrix.sync.aligned.m8n8.x4.shared.b16 {%0,%1,%2,%3}, [%4];"
        : "=r"(r[0]), "=r"(r[1]), "=r"(r[2]), "=r"(r[3]) : "r"(addr));
}
__device__ __forceinline__ void ldsm4t(uint32_t* r, uint32_t addr) {
    asm volatile("ldmatrix.sync.aligned.m8n8.x4.trans.shared.b16 {%0,%1,%2,%3}, [%4];"
        : "=r"(r[0]), "=r"(r[1]), "=r"(r[2]), "=r"(r[3]) : "r"(addr));
}
__device__ __forceinline__ void mma16816(float* d, const uint32_t* a, const uint32_t* b) {
    asm volatile("mma.sync.aligned.m16n8k16.row.col.f32.bf16.bf16.f32 "
        "{%0,%1,%2,%3}, {%4,%5,%6,%7}, {%8,%9}, {%0,%1,%2,%3};"
        : "+f"(d[0]), "+f"(d[1]), "+f"(d[2]), "+f"(d[3])
        : "r"(a[0]), "r"(a[1]), "r"(a[2]), "r"(a[3]), "r"(b[0]), "r"(b[1]));
}

// ===========================================================================
// Edge dtype detection
// ===========================================================================
__global__ void k_detect(const int* __restrict__ e32) {
    if (blockIdx.x == 0 && threadIdx.x == 0) {
        int is64 = 1;
        for (int i = 1; i < 512; i += 2)
            if (e32[i] != 0) { is64 = 0; break; }
        g_e64 = is64;
    }
}
__device__ __forceinline__ int edge_src(const int* __restrict__ e32, int e, int is64) {
    return is64 ? e32[2 * (size_t)e] : e32[e];
}
__device__ __forceinline__ int edge_dst(const int* __restrict__ e32, int e, int is64) {
    return is64 ? e32[2 * ((size_t)NE + e)] : e32[(size_t)NE + e];
}

// ===========================================================================
// CSR build
// ===========================================================================
__global__ void k_zero_counts() {
    int i = blockIdx.x * blockDim.x + threadIdx.x;
    if (i < NN) { g_deg[i] = 0; g_cursor[i] = 0; }
}
__global__ void k_count(const int* __restrict__ e32) {
    int e = blockIdx.x * blockDim.x + threadIdx.x;
    if (e < NE) {
        int dst = edge_dst(e32, e, g_e64);
        if ((unsigned)dst < NN) atomicAdd(&g_deg[dst], 1);
    }
}
__global__ void k_scan_block() {
    __shared__ int sh[256];
    int i = blockIdx.x * 256 + threadIdx.x;
    sh[threadIdx.x] = (i < NN) ? g_deg[i] : 0;
    __syncthreads();
#pragma unroll
    for (int s = 128; s > 0; s >>= 1) {
        if (threadIdx.x < s) sh[threadIdx.x] += sh[threadIdx.x + s];
        __syncthreads();
    }
    if (threadIdx.x == 0) g_part[blockIdx.x] = sh[0];
}
__global__ void k_scan_top() {
    __shared__ int sh[256];
    int t = threadIdx.x;
    sh[t] = (t < NB) ? g_part[t] : 0;
    __syncthreads();
#pragma unroll
    for (int off = 1; off < 256; off <<= 1) {
        int v = (t >= off) ? sh[t - off] : 0;
        __syncthreads();
        sh[t] += v;
        __syncthreads();
    }
    g_part[t] = (t > 0) ? sh[t - 1] : 0;
}
__global__ void k_scan_down() {
    __shared__ int sh[256];
    int t = threadIdx.x;
    int i = blockIdx.x * 256 + t;
    int d = (i < NN) ? g_deg[i] : 0;
    sh[t] = d;
    __syncthreads();
#pragma unroll
    for (int off = 1; off < 256; off <<= 1) {
        int v = (t >= off) ? sh[t - off] : 0;
        __syncthreads();
        sh[t] += v;
        __syncthreads();
    }
    int excl = g_part[blockIdx.x] + sh[t] - d;
    if (i < NN) g_off[i] = excl;
    if (i == NN - 1) g_off[NN] = excl + d;
}
__global__ void k_fill(const int* __restrict__ e32, const float* __restrict__ att) {
    int e = blockIdx.x * blockDim.x + threadIdx.x;
    if (e >= NE) return;
    int is64 = g_e64;
    int src = edge_src(e32, e, is64);
    int dst = edge_dst(e32, e, is64);
    if ((unsigned)src >= NN || (unsigned)dst >= NN) return;
    int pos = atomicAdd(&g_cursor[dst], 1);
    int slot = g_off[dst] + pos;
    g_csrc[slot] = src;
    g_catt[slot] = att[e];
}

// ===========================================================================
// Gather aggregation: one warp per destination node (mean folded in)
// ===========================================================================
__global__ __launch_bounds__(256) void k_gather(const float* __restrict__ xin) {
    const float* x = xin ? xin : g_h1;
    int t = blockIdx.x * blockDim.x + threadIdx.x;
    int n = t >> 5;
    if (n >= NN) return;
    int lane = t & 31;

    int beg = g_off[n];
    int end = g_off[n + 1];

    float4 acc = make_float4(0.f, 0.f, 0.f, 0.f);
    int i = beg;
    for (; i + 1 < end; i += 2) {
        int   s0 = g_csrc[i],     s1 = g_csrc[i + 1];
        float a0 = g_catt[i],     a1 = g_catt[i + 1];
        float4 v0 = *(const float4*)(x + (size_t)s0 * HD + lane * 4);
        float4 v1 = *(const float4*)(x + (size_t)s1 * HD + lane * 4);
        acc.x += v0.x * a0 + v1.x * a1;
        acc.y += v0.y * a0 + v1.y * a1;
        acc.z += v0.z * a0 + v1.z * a1;
        acc.w += v0.w * a0 + v1.w * a1;
    }
    if (i < end) {
        int   s0 = g_csrc[i];
        float a0 = g_catt[i];
        float4 v0 = *(const float4*)(x + (size_t)s0 * HD + lane * 4);
        acc.x += v0.x * a0;
        acc.y += v0.y * a0;
        acc.z += v0.z * a0;
        acc.w += v0.w * a0;
    }

    float inv = 1.f / fmaxf((float)(end - beg), 1.f);
    acc.x *= inv; acc.y *= inv; acc.z *= inv; acc.w *= inv;
    *(float4*)(g_agg + (size_t)n * HD + lane * 4) = acc;
}

// ===========================================================================
// Tensor-core GEMM: OUT = relu( cat(X, g_agg) @ W + bias )
// M-tile 128/CTA, N=128, K=256 in 8 chunks of 32.
// Split precision: A=Ah+Al, B=Bh+Bl (bf16); acc += AhBh + AlBh + AhBl.
// STATIC shared memory (37,888 B < 48 KB) -> no attribute call needed.
// A staged [m][k] (80B stride, ldmatrix);  B staged [k][n] (272B stride,
// ldmatrix.trans -> col-major n8k16 fragments).
// X == nullptr -> g_h1;  OUT == nullptr -> g_h1.
// ===========================================================================
#define A_STRIDE 80          // bytes per A row (32 bf16 + 8 pad)
#define B_STRIDE 272         // bytes per B row (128 bf16 + 8 pad)
#define A_BYTES  (128 * A_STRIDE)   // 10240
#define B_BYTES  (32 * B_STRIDE)    //  8704

__global__ __launch_bounds__(256) void k_gemm_tc(
    const float* __restrict__ Xin,
    const float* __restrict__ W,
    const float* __restrict__ bias,
    float* __restrict__ OUTin)
{
    __shared__ __align__(16) char sAh[A_BYTES];
    __shared__ __align__(16) char sAl[A_BYTES];
    __shared__ __align__(16) char sBh[B_BYTES];
    __shared__ __align__(16) char sBl[B_BYTES];

    const float* X   = Xin   ? Xin   : g_h1;
    float*       OUT = OUTin ? OUTin : g_h1;

    const int tid  = threadIdx.x;
    const int wid  = tid >> 5;
    const int lane = tid & 31;
    const int wm   = wid & 3;    // 4 row groups of 32
    const int wn   = wid >> 2;   // 2 col groups of 64
    const int row0 = blockIdx.x * 128;

    const uint32_t uAh = smem_to_u32(sAh);
    const uint32_t uAl = smem_to_u32(sAl);
    const uint32_t uBh = smem_to_u32(sBh);
    const uint32_t uBl = smem_to_u32(sBl);

    // per-lane ldmatrix address offsets
    const uint32_t aoff = (uint32_t)((lane & 15) * A_STRIDE + (lane >> 4) * 16);
    const uint32_t boff = (uint32_t)((lane & 15) * B_STRIDE + (lane >> 4) * 16);

    float acc[2][8][4];
#pragma unroll
    for (int mi = 0; mi < 2; mi++)
#pragma unroll
        for (int ni = 0; ni < 8; ni++)
#pragma unroll
            for (int j = 0; j < 4; j++) acc[mi][ni][j] = 0.f;

#pragma unroll 1
    for (int t = 0; t < 8; t++) {
        const float* Abase = (t < 4) ? X : g_agg;
        const int kk    = (t & 3) * 32;   // column offset within source
        const int kglob = t * 32;         // W row offset

        // --- Stage A: 128 rows x 32 cols fp32 -> Ah/Al bf16 ---
#pragma unroll
        for (int i = 0; i < 4; i++) {
            int fid = tid + i * 256;      // 1024 float4s
            int r   = fid >> 3;           // 0..127
            int c4  = fid & 7;            // cols c4*4
            int grow = row0 + r;
            float4 v = make_float4(0.f, 0.f, 0.f, 0.f);
            if (grow < NN)
                v = *(const float4*)(Abase + (size_t)grow * HD + kk + c4 * 4);
            __nv_bfloat162 h01 = __floats2bfloat162_rn(v.x, v.y);
            __nv_bfloat162 h23 = __floats2bfloat162_rn(v.z, v.w);
            __nv_bfloat162 l01 = __floats2bfloat162_rn(v.x - __bfloat162float(h01.x),
                                                       v.y - __bfloat162float(h01.y));
            __nv_bfloat162 l23 = __floats2bfloat162_rn(v.z - __bfloat162float(h23.x),
                                                       v.w - __bfloat162float(h23.y));
            uint32_t byte = (uint32_t)(r * A_STRIDE + c4 * 8);
            uint2 hv, lv;
            hv.x = *(uint32_t*)&h01; hv.y = *(uint32_t*)&h23;
            lv.x = *(uint32_t*)&l01; lv.y = *(uint32_t*)&l23;
            *(uint2*)(sAh + byte) = hv;
            *(uint2*)(sAl + byte) = lv;
        }

        // --- Stage B: W rows kglob..+31, Bs[k][n] (natural layout) ---
#pragma unroll
        for (int i = 0; i < 4; i++) {
            int eid = tid + i * 256;      // 1024 float4s
            int kr  = eid >> 5;           // 0..31
            int n4  = eid & 31;           // cols n4*4
            float4 v = *(const float4*)(W + (size_t)(kglob + kr) * HD + n4 * 4);
            __nv_bfloat162 h01 = __floats2bfloat162_rn(v.x, v.y);
            __nv_bfloat162 h23 = __floats2bfloat162_rn(v.z, v.w);
            __nv_bfloat162 l01 = __floats2bfloat162_rn(v.x - __bfloat162float(h01.x),
                                                       v.y - __bfloat162float(h01.y));
            __nv_bfloat162 l23 = __floats2bfloat162_rn(v.z - __bfloat162float(h23.x),
                                                       v.w - __bfloat162float(h23.y));
            uint32_t byte = (uint32_t)(kr * B_STRIDE + n4 * 8);
            uint2 hv, lv;
            hv.x = *(uint32_t*)&h01; hv.y = *(uint32_t*)&h23;
            lv.x = *(uint32_t*)&l01; lv.y = *(uint32_t*)&l23;
            *(uint2*)(sBh + byte) = hv;
            *(uint2*)(sBl + byte) = lv;
        }
        __syncthreads();

        // --- Compute: 3 split passes x 2 k-steps of 16 ---
#pragma unroll
        for (int pass = 0; pass < 3; pass++) {
            const uint32_t uA = (pass == 1) ? uAl : uAh;
            const uint32_t uB = (pass == 2) ? uBl : uBh;
#pragma unroll
            for (int ks = 0; ks < 2; ks++) {
                uint32_t af[2][4];
#pragma unroll
                for (int mi = 0; mi < 2; mi++)
                    ldsm4(af[mi], uA + (uint32_t)((wm * 32 + mi * 16) * A_STRIDE + ks * 32) + aoff);
                uint32_t bf[4][4];
#pragma unroll
                for (int nt = 0; nt < 4; nt++)
                    ldsm4t(bf[nt], uB + (uint32_t)(ks * 16 * B_STRIDE + (wn * 64 + nt * 16) * 2) + boff);
#pragma unroll
                for (int mi = 0; mi < 2; mi++)
#pragma unroll
                    for (int nt = 0; nt < 4; nt++) {
                        mma16816(acc[mi][2 * nt],     af[mi], &bf[nt][0]);
                        mma16816(acc[mi][2 * nt + 1], af[mi], &bf[nt][2]);
                    }
            }
        }
        __syncthreads();
    }

    // --- Epilogue: bias + relu, per-fragment float2 stores ---
#pragma unroll
    for (int mi = 0; mi < 2; mi++) {
#pragma unroll
        for (int ni = 0; ni < 8; ni++) {
            int c = wn * 64 + ni * 8 + 2 * (lane & 3);
            float2 bv = *(const float2*)(bias + c);
            int r = row0 + wm * 32 + mi * 16 + (lane >> 2);
            if (r < NN) {
                float2 o;
                o.x = fmaxf(acc[mi][ni][0] + bv.x, 0.f);
                o.y = fmaxf(acc[mi][ni][1] + bv.y, 0.f);
                *(float2*)(OUT + (size_t)r * HD + c) = o;
            }
            if (r + 8 < NN) {
                float2 o;
                o.x = fmaxf(acc[mi][ni][2] + bv.x, 0.f);
                o.y = fmaxf(acc[mi][ni][3] + bv.y, 0.f);
                *(float2*)(OUT + (size_t)(r + 8) * HD + c) = o;
            }
        }
    }
}

// ---------------------------------------------------------------------------
// Launch — kernel launches ONLY. No other CUDA API calls of any kind.
// ---------------------------------------------------------------------------
extern "C" void kernel_launch(void* const* d_in, const int* in_sizes, int n_in,
                              void* d_out, int out_size) {
    const float* data = (const float*)d_in[0];
    const int*   e32  = (const int*)d_in[1];
    const float* att  = (const float*)d_in[2];
    const float* w1   = (const float*)d_in[3];
    const float* b1   = (const float*)d_in[4];
    const float* w2   = (const float*)d_in[5];
    const float* b2   = (const float*)d_in[6];
    float*       out  = (float*)d_out;

    const int eb = (NE + 255) / 256;
    const int gather_blocks = (NN * 32 + 255) / 256;
    const int gemm_blocks   = (NN + 127) / 128;   // 391

    // CSR build (shared by both layers)
    k_detect<<<1, 32>>>(e32);
    k_zero_counts<<<NB, 256>>>();
    k_count<<<eb, 256>>>(e32);
    k_scan_block<<<NB, 256>>>();
    k_scan_top<<<1, 256>>>();
    k_scan_down<<<NB, 256>>>();
    k_fill<<<eb, 256>>>(e32, att);

    // Layer 1
    k_gather<<<gather_blocks, 256>>>(data);
    k_gemm_tc<<<gemm_blocks, 256>>>(data, w1, b1, nullptr);

    // Layer 2
    k_gather<<<gather_blocks, 256>>>(nullptr);
    k_gemm_tc<<<gemm_blocks, 256>>>(nullptr, w2, b2, out);
}

// round 9
// speedup vs baseline: 3.2101x; 1.0508x over previous
#include <cuda_runtime.h>
#include <cuda_bf16.h>
#include <cstdint>
#include <cstddef>

// Problem constants (fixed by the reference setup_inputs)
#define NN 50000
#define HD 128
#define NE 640000
#define NB 196   // (NN + 255) / 256

// Scratch (device globals — no allocation allowed)
__device__ float g_agg[(size_t)NN * HD];
__device__ float g_h1[(size_t)NN * HD];
__device__ int   g_deg[NN];
__device__ int   g_cursor[NN];
__device__ int   g_off[NN + 1];
__device__ int   g_part[256];
__device__ int   g_csrc[NE];   // CSR: src node per slot
__device__ float g_catt[NE];   // CSR: att weight per slot
__device__ int   g_e64;        // 1 if edge buffer is int64, 0 if int32
__device__ __nv_bfloat16 g_wh[2 * 256 * HD];  // W hi, both layers
__device__ __nv_bfloat16 g_wl[2 * 256 * HD];  // W lo residual

// ===========================================================================
// Warp-level MMA helpers (baseline PTX, valid on plain compute_103)
// ===========================================================================
__device__ __forceinline__ uint32_t smem_to_u32(const void* p) {
    uint32_t a;
    asm("{ .reg .u64 t; cvta.to.shared.u64 t, %1; cvt.u32.u64 %0, t; }"
        : "=r"(a) : "l"(p));
    return a;
}
__device__ __forceinline__ void ldsm4(uint32_t* r, uint32_t addr) {
    asm volatile("ldmatrix.sync.aligned.m8n8.x4.shared.b16 {%0,%1,%2,%3}, [%4];"
        : "=r"(r[0]), "=r"(r[1]), "=r"(r[2]), "=r"(r[3]) : "r"(addr));
}
__device__ __forceinline__ void ldsm4t(uint32_t* r, uint32_t addr) {
    asm volatile("ldmatrix.sync.aligned.m8n8.x4.trans.shared.b16 {%0,%1,%2,%3}, [%4];"
        : "=r"(r[0]), "=r"(r[1]), "=r"(r[2]), "=r"(r[3]) : "r"(addr));
}
__device__ __forceinline__ void mma16816(float* d, const uint32_t* a, const uint32_t* b) {
    asm volatile("mma.sync.aligned.m16n8k16.row.col.f32.bf16.bf16.f32 "
        "{%0,%1,%2,%3}, {%4,%5,%6,%7}, {%8,%9}, {%0,%1,%2,%3};"
        : "+f"(d[0]), "+f"(d[1]), "+f"(d[2]), "+f"(d[3])
        : "r"(a[0]), "r"(a[1]), "r"(a[2]), "r"(a[3]), "r"(b[0]), "r"(b[1]));
}

// ===========================================================================
// Edge helpers
// ===========================================================================
__device__ __forceinline__ int edge_src(const int* __restrict__ e32, int e, int is64) {
    return is64 ? e32[2 * (size_t)e] : e32[e];
}
__device__ __forceinline__ int edge_dst(const int* __restrict__ e32, int e, int is64) {
    return is64 ? e32[2 * ((size_t)NE + e)] : e32[(size_t)NE + e];
}

// ===========================================================================
// W split precompute: w1/w2 fp32 -> (hi, lo) bf16
// ===========================================================================
__global__ void k_prep_w(const float* __restrict__ w1, const float* __restrict__ w2) {
    int i = blockIdx.x * blockDim.x + threadIdx.x;     // 0..65535
    if (i >= 2 * 256 * HD) return;
    float v = (i < 256 * HD) ? w1[i] : w2[i - 256 * HD];
    __nv_bfloat16 h = __float2bfloat16(v);
    __nv_bfloat16 l = __float2bfloat16(v - __bfloat162float(h));
    g_wh[i] = h;
    g_wl[i] = l;
}

// ===========================================================================
// CSR build
// ===========================================================================
__global__ void k_zero_counts(const int* __restrict__ e32) {
    int i = blockIdx.x * blockDim.x + threadIdx.x;
    if (i < NN) { g_deg[i] = 0; g_cursor[i] = 0; }
    if (blockIdx.x == 0 && threadIdx.x == 0) {
        // dtype detect: int64 edges (<2^31) have zero odd words
        int is64 = 1;
        for (int j = 1; j < 512; j += 2)
            if (e32[j] != 0) { is64 = 0; break; }
        g_e64 = is64;
    }
}
__global__ void k_count(const int* __restrict__ e32) {
    int e = blockIdx.x * blockDim.x + threadIdx.x;
    if (e < NE) {
        int dst = edge_dst(e32, e, g_e64);
        if ((unsigned)dst < NN) atomicAdd(&g_deg[dst], 1);
    }
}
__global__ void k_scan_block() {
    __shared__ int sh[256];
    int i = blockIdx.x * 256 + threadIdx.x;
    sh[threadIdx.x] = (i < NN) ? g_deg[i] : 0;
    __syncthreads();
#pragma unroll
    for (int s = 128; s > 0; s >>= 1) {
        if (threadIdx.x < s) sh[threadIdx.x] += sh[threadIdx.x + s];
        __syncthreads();
    }
    if (threadIdx.x == 0) g_part[blockIdx.x] = sh[0];
}
// Per-block: base = sum(g_part[0..bid)) computed redundantly, then local scan.
__global__ void k_scan_down() {
    __shared__ int sh[256];
    __shared__ int base_sh;
    int t = threadIdx.x;

    int p = (t < NB && t < blockIdx.x) ? g_part[t] : 0;
    sh[t] = p;
    __syncthreads();
#pragma unroll
    for (int s = 128; s > 0; s >>= 1) {
        if (t < s) sh[t] += sh[t + s];
        __syncthreads();
    }
    if (t == 0) base_sh = sh[0];
    __syncthreads();
    int base = base_sh;
    __syncthreads();

    int i = blockIdx.x * 256 + t;
    int d = (i < NN) ? g_deg[i] : 0;
    sh[t] = d;
    __syncthreads();
#pragma unroll
    for (int off = 1; off < 256; off <<= 1) {
        int v = (t >= off) ? sh[t - off] : 0;
        __syncthreads();
        sh[t] += v;
        __syncthreads();
    }
    int excl = base + sh[t] - d;
    if (i < NN) g_off[i] = excl;
    if (i == NN - 1) g_off[NN] = excl + d;
}
__global__ void k_fill(const int* __restrict__ e32, const float* __restrict__ att) {
    int e = blockIdx.x * blockDim.x + threadIdx.x;
    if (e >= NE) return;
    int is64 = g_e64;
    int src = edge_src(e32, e, is64);
    int dst = edge_dst(e32, e, is64);
    if ((unsigned)src >= NN || (unsigned)dst >= NN) return;
    int pos = atomicAdd(&g_cursor[dst], 1);
    int slot = g_off[dst] + pos;
    g_csrc[slot] = src;
    g_catt[slot] = att[e];
}

// ===========================================================================
// Gather aggregation: one warp per destination node (mean folded in), MLP=4
// ===========================================================================
__global__ __launch_bounds__(256) void k_gather(const float* __restrict__ xin) {
    const float* x = xin ? xin : g_h1;
    int t = blockIdx.x * blockDim.x + threadIdx.x;
    int n = t >> 5;
    if (n >= NN) return;
    int lane = t & 31;

    int beg = g_off[n];
    int end = g_off[n + 1];

    float4 acc = make_float4(0.f, 0.f, 0.f, 0.f);
    int i = beg;
    for (; i + 3 < end; i += 4) {
        int   s0 = g_csrc[i],   s1 = g_csrc[i+1], s2 = g_csrc[i+2], s3 = g_csrc[i+3];
        float a0 = g_catt[i],   a1 = g_catt[i+1], a2 = g_catt[i+2], a3 = g_catt[i+3];
        float4 v0 = *(const float4*)(x + (size_t)s0 * HD + lane * 4);
        float4 v1 = *(const float4*)(x + (size_t)s1 * HD + lane * 4);
        float4 v2 = *(const float4*)(x + (size_t)s2 * HD + lane * 4);
        float4 v3 = *(const float4*)(x + (size_t)s3 * HD + lane * 4);
        acc.x += v0.x * a0 + v1.x * a1 + v2.x * a2 + v3.x * a3;
        acc.y += v0.y * a0 + v1.y * a1 + v2.y * a2 + v3.y * a3;
        acc.z += v0.z * a0 + v1.z * a1 + v2.z * a2 + v3.z * a3;
        acc.w += v0.w * a0 + v1.w * a1 + v2.w * a2 + v3.w * a3;
    }
    for (; i < end; i++) {
        int   s0 = g_csrc[i];
        float a0 = g_catt[i];
        float4 v0 = *(const float4*)(x + (size_t)s0 * HD + lane * 4);
        acc.x += v0.x * a0;
        acc.y += v0.y * a0;
        acc.z += v0.z * a0;
        acc.w += v0.w * a0;
    }

    float inv = 1.f / fmaxf((float)(end - beg), 1.f);
    acc.x *= inv; acc.y *= inv; acc.z *= inv; acc.w *= inv;
    *(float4*)(g_agg + (size_t)n * HD + lane * 4) = acc;
}

// ===========================================================================
// Tensor-core GEMM: OUT = relu( cat(X, g_agg) @ W + bias )
// M-tile 128/CTA, N=128, K=256 in 8 chunks of 32.
// Split precision: A=Ah+Al, W=Wh+Wl (bf16); acc += AhWh + AlWh + AhWl.
// Fragments loaded ONCE per k-step (12 ldsm), all 3 passes from registers.
// W hi/lo precomputed in g_wh/g_wl (woff selects layer).
// STATIC shared memory (37,888 B) -> no attribute call needed.
// X == nullptr -> g_h1;  OUT == nullptr -> g_h1.
// ===========================================================================
#define A_STRIDE 80          // bytes per A row (32 bf16 + 8 pad)
#define B_STRIDE 272         // bytes per B row (128 bf16 + 8 pad)
#define A_BYTES  (128 * A_STRIDE)   // 10240
#define B_BYTES  (32 * B_STRIDE)    //  8704

__global__ __launch_bounds__(256) void k_gemm_tc(
    const float* __restrict__ Xin,
    int woff,                        // 0 (layer1) or 256*HD (layer2)
    const float* __restrict__ bias,
    float* __restrict__ OUTin)
{
    __shared__ __align__(16) char sAh[A_BYTES];
    __shared__ __align__(16) char sAl[A_BYTES];
    __shared__ __align__(16) char sBh[B_BYTES];
    __shared__ __align__(16) char sBl[B_BYTES];

    const float* X   = Xin   ? Xin   : g_h1;
    float*       OUT = OUTin ? OUTin : g_h1;
    const __nv_bfloat16* Wh = g_wh + woff;
    const __nv_bfloat16* Wl = g_wl + woff;

    const int tid  = threadIdx.x;
    const int wid  = tid >> 5;
    const int lane = tid & 31;
    const int wm   = wid & 3;    // 4 row groups of 32
    const int wn   = wid >> 2;   // 2 col groups of 64
    const int row0 = blockIdx.x * 128;

    const uint32_t uAh = smem_to_u32(sAh);
    const uint32_t uAl = smem_to_u32(sAl);
    const uint32_t uBh = smem_to_u32(sBh);
    const uint32_t uBl = smem_to_u32(sBl);

    // per-lane ldmatrix address offsets
    const uint32_t aoff = (uint32_t)((lane & 15) * A_STRIDE + (lane >> 4) * 16);
    const uint32_t boff = (uint32_t)((lane & 15) * B_STRIDE + (lane >> 4) * 16);

    float acc[2][8][4];
#pragma unroll
    for (int mi = 0; mi < 2; mi++)
#pragma unroll
        for (int ni = 0; ni < 8; ni++)
#pragma unroll
            for (int j = 0; j < 4; j++) acc[mi][ni][j] = 0.f;

#pragma unroll 1
    for (int t = 0; t < 8; t++) {
        const float* Abase = (t < 4) ? X : g_agg;
        const int kk    = (t & 3) * 32;   // column offset within source
        const int kglob = t * 32;         // W row offset

        // --- Stage A: 128 rows x 32 cols fp32 -> Ah/Al bf16 ---
#pragma unroll
        for (int i = 0; i < 4; i++) {
            int fid = tid + i * 256;      // 1024 float4s
            int r   = fid >> 3;           // 0..127
            int c4  = fid & 7;            // cols c4*4
            int grow = row0 + r;
            float4 v = make_float4(0.f, 0.f, 0.f, 0.f);
            if (grow < NN)
                v = *(const float4*)(Abase + (size_t)grow * HD + kk + c4 * 4);
            __nv_bfloat162 h01 = __floats2bfloat162_rn(v.x, v.y);
            __nv_bfloat162 h23 = __floats2bfloat162_rn(v.z, v.w);
            __nv_bfloat162 l01 = __floats2bfloat162_rn(v.x - __bfloat162float(h01.x),
                                                       v.y - __bfloat162float(h01.y));
            __nv_bfloat162 l23 = __floats2bfloat162_rn(v.z - __bfloat162float(h23.x),
                                                       v.w - __bfloat162float(h23.y));
            uint32_t byte = (uint32_t)(r * A_STRIDE + c4 * 8);
            uint2 hv, lv;
            hv.x = *(uint32_t*)&h01; hv.y = *(uint32_t*)&h23;
            lv.x = *(uint32_t*)&l01; lv.y = *(uint32_t*)&l23;
            *(uint2*)(sAh + byte) = hv;
            *(uint2*)(sAl + byte) = lv;
        }

        // --- Stage B: precomputed bf16 hi/lo, pure copy ---
#pragma unroll
        for (int i = 0; i < 4; i++) {
            int eid = tid + i * 256;      // 1024 groups of 4 elements
            int kr  = eid >> 5;           // 0..31
            int n4  = eid & 31;           // cols n4*4
            size_t gidx = (size_t)(kglob + kr) * HD + n4 * 4;
            uint32_t byte = (uint32_t)(kr * B_STRIDE + n4 * 8);
            *(uint2*)(sBh + byte) = *(const uint2*)(Wh + gidx);
            *(uint2*)(sBl + byte) = *(const uint2*)(Wl + gidx);
        }
        __syncthreads();

        // --- Compute: load fragments once, 3 split passes from registers ---
#pragma unroll
        for (int ks = 0; ks < 2; ks++) {
            uint32_t afh[2][4], afl[2][4];
#pragma unroll
            for (int mi = 0; mi < 2; mi++) {
                uint32_t ab = (uint32_t)((wm * 32 + mi * 16) * A_STRIDE + ks * 32) + aoff;
                ldsm4(afh[mi], uAh + ab);
                ldsm4(afl[mi], uAl + ab);
            }
            uint32_t bfh[4][4], bfl[4][4];
#pragma unroll
            for (int nt = 0; nt < 4; nt++) {
                uint32_t bb = (uint32_t)(ks * 16 * B_STRIDE + (wn * 64 + nt * 16) * 2) + boff;
                ldsm4t(bfh[nt], uBh + bb);
                ldsm4t(bfl[nt], uBl + bb);
            }
#pragma unroll
            for (int mi = 0; mi < 2; mi++)
#pragma unroll
                for (int nt = 0; nt < 4; nt++) {
                    mma16816(acc[mi][2*nt],   afh[mi], &bfh[nt][0]);
                    mma16816(acc[mi][2*nt+1], afh[mi], &bfh[nt][2]);
                    mma16816(acc[mi][2*nt],   afl[mi], &bfh[nt][0]);
                    mma16816(acc[mi][2*nt+1], afl[mi], &bfh[nt][2]);
                    mma16816(acc[mi][2*nt],   afh[mi], &bfl[nt][0]);
                    mma16816(acc[mi][2*nt+1], afh[mi], &bfl[nt][2]);
                }
        }
        __syncthreads();
    }

    // --- Epilogue: bias + relu, per-fragment float2 stores ---
#pragma unroll
    for (int mi = 0; mi < 2; mi++) {
#pragma unroll
        for (int ni = 0; ni < 8; ni++) {
            int c = wn * 64 + ni * 8 + 2 * (lane & 3);
            float2 bv = *(const float2*)(bias + c);
            int r = row0 + wm * 32 + mi * 16 + (lane >> 2);
            if (r < NN) {
                float2 o;
                o.x = fmaxf(acc[mi][ni][0] + bv.x, 0.f);
                o.y = fmaxf(acc[mi][ni][1] + bv.y, 0.f);
                *(float2*)(OUT + (size_t)r * HD + c) = o;
            }
            if (r + 8 < NN) {
                float2 o;
                o.x = fmaxf(acc[mi][ni][2] + bv.x, 0.f);
                o.y = fmaxf(acc[mi][ni][3] + bv.y, 0.f);
                *(float2*)(OUT + (size_t)(r + 8) * HD + c) = o;
            }
        }
    }
}

// ---------------------------------------------------------------------------
// Launch — kernel launches ONLY. No other CUDA API calls of any kind.
// ---------------------------------------------------------------------------
extern "C" void kernel_launch(void* const* d_in, const int* in_sizes, int n_in,
                              void* d_out, int out_size) {
    const float* data = (const float*)d_in[0];
    const int*   e32  = (const int*)d_in[1];
    const float* att  = (const float*)d_in[2];
    const float* w1   = (const float*)d_in[3];
    const float* b1   = (const float*)d_in[4];
    const float* w2   = (const float*)d_in[5];
    const float* b2   = (const float*)d_in[6];
    float*       out  = (float*)d_out;

    const int eb = (NE + 255) / 256;
    const int gather_blocks = (NN * 32 + 255) / 256;
    const int gemm_blocks   = (NN + 127) / 128;   // 391

    // W split precompute + CSR build (shared by both layers)
    k_prep_w<<<(2 * 256 * HD + 255) / 256, 256>>>(w1, w2);
    k_zero_counts<<<NB, 256>>>(e32);
    k_count<<<eb, 256>>>(e32);
    k_scan_block<<<NB, 256>>>();
    k_scan_down<<<NB, 256>>>();
    k_fill<<<eb, 256>>>(e32, att);

    // Layer 1
    k_gather<<<gather_blocks, 256>>>(data);
    k_gemm_tc<<<gemm_blocks, 256>>>(data, 0, b1, nullptr);

    // Layer 2
    k_gather<<<gather_blocks, 256>>>(nullptr);
    k_gemm_tc<<<gemm_blocks, 256>>>(nullptr, 256 * HD, b2, out);
}

// round 11
// speedup vs baseline: 3.3579x; 1.0461x over previous
#include <cuda_runtime.h>
#include <cuda_bf16.h>
#include <cstdint>
#include <cstddef>

// Problem constants (fixed by the reference setup_inputs)
#define NN 50000
#define HD 128
#define NE 640000
#define NB 196   // (NN + 255) / 256

// Scratch (device globals — no allocation allowed)
__device__ float g_agg[(size_t)NN * HD];
__device__ float g_h1[(size_t)NN * HD];
__device__ int   g_deg[NN];
__device__ int   g_cursor[NN];
__device__ int   g_off[NN + 1];
__device__ int   g_part[256];
__device__ int   g_csrc[NE];   // CSR: src node per slot
__device__ float g_catt[NE];   // CSR: att weight per slot
__device__ int   g_e64;        // 1 if edge buffer is int64, 0 if int32
__device__ __nv_bfloat16 g_wh[2 * 256 * HD];  // W hi, both layers
__device__ __nv_bfloat16 g_wl[2 * 256 * HD];  // W lo residual

// ===========================================================================
// Warp-level MMA helpers (baseline PTX, valid on plain compute_103)
// ===========================================================================
__device__ __forceinline__ uint32_t smem_to_u32(const void* p) {
    uint32_t a;
    asm("{ .reg .u64 t; cvta.to.shared.u64 t, %1; cvt.u32.u64 %0, t; }"
        : "=r"(a) : "l"(p));
    return a;
}
__device__ __forceinline__ void ldsm4(uint32_t* r, uint32_t addr) {
    asm volatile("ldmatrix.sync.aligned.m8n8.x4.shared.b16 {%0,%1,%2,%3}, [%4];"
        : "=r"(r[0]), "=r"(r[1]), "=r"(r[2]), "=r"(r[3]) : "r"(addr));
}
__device__ __forceinline__ void ldsm4t(uint32_t* r, uint32_t addr) {
    asm volatile("ldmatrix.sync.aligned.m8n8.x4.trans.shared.b16 {%0,%1,%2,%3}, [%4];"
        : "=r"(r[0]), "=r"(r[1]), "=r"(r[2]), "=r"(r[3]) : "r"(addr));
}
__device__ __forceinline__ void mma16816(float* d, const uint32_t* a, const uint32_t* b) {
    asm volatile("mma.sync.aligned.m16n8k16.row.col.f32.bf16.bf16.f32 "
        "{%0,%1,%2,%3}, {%4,%5,%6,%7}, {%8,%9}, {%0,%1,%2,%3};"
        : "+f"(d[0]), "+f"(d[1]), "+f"(d[2]), "+f"(d[3])
        : "r"(a[0]), "r"(a[1]), "r"(a[2]), "r"(a[3]), "r"(b[0]), "r"(b[1]));
}

// ===========================================================================
// Edge helpers
// ===========================================================================
__device__ __forceinline__ int edge_src(const int* __restrict__ e32, int e, int is64) {
    return is64 ? e32[2 * (size_t)e] : e32[e];
}
__device__ __forceinline__ int edge_dst(const int* __restrict__ e32, int e, int is64) {
    return is64 ? e32[2 * ((size_t)NE + e)] : e32[(size_t)NE + e];
}

// ===========================================================================
// Init: W split precompute + CSR counters zero + edge dtype detect (fused)
// grid = 256 blocks x 256 threads = 65536 threads (== 2*256*HD elements)
// ===========================================================================
__global__ void k_init(const float* __restrict__ w1, const float* __restrict__ w2,
                       const int* __restrict__ e32) {
    int i = blockIdx.x * blockDim.x + threadIdx.x;
    // W hi/lo split
    float v = (i < 256 * HD) ? w1[i] : w2[i - 256 * HD];
    __nv_bfloat16 h = __float2bfloat16(v);
    __nv_bfloat16 l = __float2bfloat16(v - __bfloat162float(h));
    g_wh[i] = h;
    g_wl[i] = l;
    // CSR counter zeroing
    if (i < NN) { g_deg[i] = 0; g_cursor[i] = 0; }
    // dtype detect: int64 edges (<2^31) have zero odd words
    if (i == 0) {
        int is64 = 1;
        for (int j = 1; j < 512; j += 2)
            if (e32[j] != 0) { is64 = 0; break; }
        g_e64 = is64;
    }
}

// ===========================================================================
// CSR build
// ===========================================================================
__global__ void k_count(const int* __restrict__ e32) {
    int e = blockIdx.x * blockDim.x + threadIdx.x;
    if (e < NE) {
        int dst = edge_dst(e32, e, g_e64);
        if ((unsigned)dst < NN) atomicAdd(&g_deg[dst], 1);
    }
}
__global__ void k_scan_block() {
    __shared__ int sh[256];
    int i = blockIdx.x * 256 + threadIdx.x;
    sh[threadIdx.x] = (i < NN) ? g_deg[i] : 0;
    __syncthreads();
#pragma unroll
    for (int s = 128; s > 0; s >>= 1) {
        if (threadIdx.x < s) sh[threadIdx.x] += sh[threadIdx.x + s];
        __syncthreads();
    }
    if (threadIdx.x == 0) g_part[blockIdx.x] = sh[0];
}
// Per-block: base = sum(g_part[0..bid)) computed redundantly, then local scan.
__global__ void k_scan_down() {
    __shared__ int sh[256];
    __shared__ int base_sh;
    int t = threadIdx.x;

    int p = (t < NB && t < blockIdx.x) ? g_part[t] : 0;
    sh[t] = p;
    __syncthreads();
#pragma unroll
    for (int s = 128; s > 0; s >>= 1) {
        if (t < s) sh[t] += sh[t + s];
        __syncthreads();
    }
    if (t == 0) base_sh = sh[0];
    __syncthreads();
    int base = base_sh;
    __syncthreads();

    int i = blockIdx.x * 256 + t;
    int d = (i < NN) ? g_deg[i] : 0;
    sh[t] = d;
    __syncthreads();
#pragma unroll
    for (int off = 1; off < 256; off <<= 1) {
        int v = (t >= off) ? sh[t - off] : 0;
        __syncthreads();
        sh[t] += v;
        __syncthreads();
    }
    int excl = base + sh[t] - d;
    if (i < NN) g_off[i] = excl;
    if (i == NN - 1) g_off[NN] = excl + d;
}
__global__ void k_fill(const int* __restrict__ e32, const float* __restrict__ att) {
    int e = blockIdx.x * blockDim.x + threadIdx.x;
    if (e >= NE) return;
    int is64 = g_e64;
    int src = edge_src(e32, e, is64);
    int dst = edge_dst(e32, e, is64);
    if ((unsigned)src >= NN || (unsigned)dst >= NN) return;
    int pos = atomicAdd(&g_cursor[dst], 1);
    int slot = g_off[dst] + pos;
    g_csrc[slot] = src;
    g_catt[slot] = att[e];
}

// ===========================================================================
// Gather aggregation: one warp per destination node (mean folded in), MLP=4
// ===========================================================================
__global__ __launch_bounds__(256) void k_gather(const float* __restrict__ xin) {
    const float* x = xin ? xin : g_h1;
    int t = blockIdx.x * blockDim.x + threadIdx.x;
    int n = t >> 5;
    if (n >= NN) return;
    int lane = t & 31;

    int beg = g_off[n];
    int end = g_off[n + 1];

    float4 acc = make_float4(0.f, 0.f, 0.f, 0.f);
    int i = beg;
    for (; i + 3 < end; i += 4) {
        int   s0 = g_csrc[i],   s1 = g_csrc[i+1], s2 = g_csrc[i+2], s3 = g_csrc[i+3];
        float a0 = g_catt[i],   a1 = g_catt[i+1], a2 = g_catt[i+2], a3 = g_catt[i+3];
        float4 v0 = *(const float4*)(x + (size_t)s0 * HD + lane * 4);
        float4 v1 = *(const float4*)(x + (size_t)s1 * HD + lane * 4);
        float4 v2 = *(const float4*)(x + (size_t)s2 * HD + lane * 4);
        float4 v3 = *(const float4*)(x + (size_t)s3 * HD + lane * 4);
        acc.x += v0.x * a0 + v1.x * a1 + v2.x * a2 + v3.x * a3;
        acc.y += v0.y * a0 + v1.y * a1 + v2.y * a2 + v3.y * a3;
        acc.z += v0.z * a0 + v1.z * a1 + v2.z * a2 + v3.z * a3;
        acc.w += v0.w * a0 + v1.w * a1 + v2.w * a2 + v3.w * a3;
    }
    for (; i < end; i++) {
        int   s0 = g_csrc[i];
        float a0 = g_catt[i];
        float4 v0 = *(const float4*)(x + (size_t)s0 * HD + lane * 4);
        acc.x += v0.x * a0;
        acc.y += v0.y * a0;
        acc.z += v0.z * a0;
        acc.w += v0.w * a0;
    }

    float inv = 1.f / fmaxf((float)(end - beg), 1.f);
    acc.x *= inv; acc.y *= inv; acc.z *= inv; acc.w *= inv;
    *(float4*)(g_agg + (size_t)n * HD + lane * 4) = acc;
}

// ===========================================================================
// Tensor-core GEMM: OUT = relu( cat(X, g_agg) @ W + bias )
// M-tile 128/CTA, N=128, K=256 in 8 chunks of 32.
// Split precision: A=Ah+Al, W=Wh+Wl (bf16); acc += AhWh + AlWh + AhWl.
// SOFTWARE PIPELINED: chunk t+1's global loads prefetched into registers
// while chunk t's MMAs execute. Static smem (37,888 B), no attribute call.
// X == nullptr -> g_h1;  OUT == nullptr -> g_h1.
// ===========================================================================
#define A_STRIDE 80          // bytes per A row (32 bf16 + 8 pad)
#define B_STRIDE 272         // bytes per B row (128 bf16 + 8 pad)
#define A_BYTES  (128 * A_STRIDE)   // 10240
#define B_BYTES  (32 * B_STRIDE)    //  8704

__global__ __launch_bounds__(256) void k_gemm_tc(
    const float* __restrict__ Xin,
    int woff,                        // 0 (layer1) or 256*HD (layer2)
    const float* __restrict__ bias,
    float* __restrict__ OUTin)
{
    __shared__ __align__(16) char sAh[A_BYTES];
    __shared__ __align__(16) char sAl[A_BYTES];
    __shared__ __align__(16) char sBh[B_BYTES];
    __shared__ __align__(16) char sBl[B_BYTES];

    const float* X   = Xin   ? Xin   : g_h1;
    float*       OUT = OUTin ? OUTin : g_h1;
    const __nv_bfloat16* Wh = g_wh + woff;
    const __nv_bfloat16* Wl = g_wl + woff;

    const int tid  = threadIdx.x;
    const int wid  = tid >> 5;
    const int lane = tid & 31;
    const int wm   = wid & 3;    // 4 row groups of 32
    const int wn   = wid >> 2;   // 2 col groups of 64
    const int row0 = blockIdx.x * 128;

    const uint32_t uAh = smem_to_u32(sAh);
    const uint32_t uAl = smem_to_u32(sAl);
    const uint32_t uBh = smem_to_u32(sBh);
    const uint32_t uBl = smem_to_u32(sBl);

    // per-lane ldmatrix address offsets
    const uint32_t aoff = (uint32_t)((lane & 15) * A_STRIDE + (lane >> 4) * 16);
    const uint32_t boff = (uint32_t)((lane & 15) * B_STRIDE + (lane >> 4) * 16);

    // Per-thread staging indices (identical for every chunk)
    int a_r[4], a_c4[4];
    int b_kr[4], b_n4[4];
#pragma unroll
    for (int i = 0; i < 4; i++) {
        int fid = tid + i * 256;
        a_r[i]  = fid >> 3;
        a_c4[i] = fid & 7;
        b_kr[i] = fid >> 5;
        b_n4[i] = fid & 31;
    }

    float acc[2][8][4];
#pragma unroll
    for (int mi = 0; mi < 2; mi++)
#pragma unroll
        for (int ni = 0; ni < 8; ni++)
#pragma unroll
            for (int j = 0; j < 4; j++) acc[mi][ni][j] = 0.f;

    float4 pa[4];
    uint2  pbh[4], pbl[4];

    // Prefetch chunk 0
    {
        const float* Abase = X;
#pragma unroll
        for (int i = 0; i < 4; i++) {
            int grow = row0 + a_r[i];
            pa[i] = make_float4(0.f, 0.f, 0.f, 0.f);
            if (grow < NN)
                pa[i] = *(const float4*)(Abase + (size_t)grow * HD + a_c4[i] * 4);
            size_t gidx = (size_t)b_kr[i] * HD + b_n4[i] * 4;
            pbh[i] = *(const uint2*)(Wh + gidx);
            pbl[i] = *(const uint2*)(Wl + gidx);
        }
    }

#pragma unroll 1
    for (int t = 0; t < 8; t++) {
        // --- Store prefetched chunk t to smem (with A conversion) ---
#pragma unroll
        for (int i = 0; i < 4; i++) {
            float4 v = pa[i];
            __nv_bfloat162 h01 = __floats2bfloat162_rn(v.x, v.y);
            __nv_bfloat162 h23 = __floats2bfloat162_rn(v.z, v.w);
            __nv_bfloat162 l01 = __floats2bfloat162_rn(v.x - __bfloat162float(h01.x),
                                                       v.y - __bfloat162float(h01.y));
            __nv_bfloat162 l23 = __floats2bfloat162_rn(v.z - __bfloat162float(h23.x),
                                                       v.w - __bfloat162float(h23.y));
            uint32_t abyte = (uint32_t)(a_r[i] * A_STRIDE + a_c4[i] * 8);
            uint2 hv, lv;
            hv.x = *(uint32_t*)&h01; hv.y = *(uint32_t*)&h23;
            lv.x = *(uint32_t*)&l01; lv.y = *(uint32_t*)&l23;
            *(uint2*)(sAh + abyte) = hv;
            *(uint2*)(sAl + abyte) = lv;
            uint32_t bbyte = (uint32_t)(b_kr[i] * B_STRIDE + b_n4[i] * 8);
            *(uint2*)(sBh + bbyte) = pbh[i];
            *(uint2*)(sBl + bbyte) = pbl[i];
        }
        __syncthreads();

        // --- Prefetch chunk t+1 (loads in flight during MMA phase) ---
        if (t < 7) {
            int tn = t + 1;
            const float* Abase = (tn < 4) ? X : g_agg;
            const int kk    = (tn & 3) * 32;
            const int kglob = tn * 32;
#pragma unroll
            for (int i = 0; i < 4; i++) {
                int grow = row0 + a_r[i];
                pa[i] = make_float4(0.f, 0.f, 0.f, 0.f);
                if (grow < NN)
                    pa[i] = *(const float4*)(Abase + (size_t)grow * HD + kk + a_c4[i] * 4);
                size_t gidx = (size_t)(kglob + b_kr[i]) * HD + b_n4[i] * 4;
                pbh[i] = *(const uint2*)(Wh + gidx);
                pbl[i] = *(const uint2*)(Wl + gidx);
            }
        }

        // --- Compute chunk t: fragments once, 3 split passes ---
#pragma unroll
        for (int ks = 0; ks < 2; ks++) {
            uint32_t afh[2][4], afl[2][4];
#pragma unroll
            for (int mi = 0; mi < 2; mi++) {
                uint32_t ab = (uint32_t)((wm * 32 + mi * 16) * A_STRIDE + ks * 32) + aoff;
                ldsm4(afh[mi], uAh + ab);
                ldsm4(afl[mi], uAl + ab);
            }
            uint32_t bfh[4][4], bfl[4][4];
#pragma unroll
            for (int nt = 0; nt < 4; nt++) {
                uint32_t bb = (uint32_t)(ks * 16 * B_STRIDE + (wn * 64 + nt * 16) * 2) + boff;
                ldsm4t(bfh[nt], uBh + bb);
                ldsm4t(bfl[nt], uBl + bb);
            }
#pragma unroll
            for (int mi = 0; mi < 2; mi++)
#pragma unroll
                for (int nt = 0; nt < 4; nt++) {
                    mma16816(acc[mi][2*nt],   afh[mi], &bfh[nt][0]);
                    mma16816(acc[mi][2*nt+1], afh[mi], &bfh[nt][2]);
                    mma16816(acc[mi][2*nt],   afl[mi], &bfh[nt][0]);
                    mma16816(acc[mi][2*nt+1], afl[mi], &bfh[nt][2]);
                    mma16816(acc[mi][2*nt],   afh[mi], &bfl[nt][0]);
                    mma16816(acc[mi][2*nt+1], afh[mi], &bfl[nt][2]);
                }
        }
        __syncthreads();
    }

    // --- Epilogue: bias + relu, per-fragment float2 stores ---
#pragma unroll
    for (int mi = 0; mi < 2; mi++) {
#pragma unroll
        for (int ni = 0; ni < 8; ni++) {
            int c = wn * 64 + ni * 8 + 2 * (lane & 3);
            float2 bv = *(const float2*)(bias + c);
            int r = row0 + wm * 32 + mi * 16 + (lane >> 2);
            if (r < NN) {
                float2 o;
                o.x = fmaxf(acc[mi][ni][0] + bv.x, 0.f);
                o.y = fmaxf(acc[mi][ni][1] + bv.y, 0.f);
                *(float2*)(OUT + (size_t)r * HD + c) = o;
            }
            if (r + 8 < NN) {
                float2 o;
                o.x = fmaxf(acc[mi][ni][2] + bv.x, 0.f);
                o.y = fmaxf(acc[mi][ni][3] + bv.y, 0.f);
                *(float2*)(OUT + (size_t)(r + 8) * HD + c) = o;
            }
        }
    }
}

// ---------------------------------------------------------------------------
// Launch — kernel launches ONLY. No other CUDA API calls of any kind.
// ---------------------------------------------------------------------------
extern "C" void kernel_launch(void* const* d_in, const int* in_sizes, int n_in,
                              void* d_out, int out_size) {
    const float* data = (const float*)d_in[0];
    const int*   e32  = (const int*)d_in[1];
    const float* att  = (const float*)d_in[2];
    const float* w1   = (const float*)d_in[3];
    const float* b1   = (const float*)d_in[4];
    const float* w2   = (const float*)d_in[5];
    const float* b2   = (const float*)d_in[6];
    float*       out  = (float*)d_out;

    const int eb = (NE + 255) / 256;
    const int gather_blocks = (NN * 32 + 255) / 256;
    const int gemm_blocks   = (NN + 127) / 128;   // 391

    // Init (W split + CSR zero + dtype detect) and CSR build
    k_init<<<256, 256>>>(w1, w2, e32);
    k_count<<<eb, 256>>>(e32);
    k_scan_block<<<NB, 256>>>();
    k_scan_down<<<NB, 256>>>();
    k_fill<<<eb, 256>>>(e32, att);

    // Layer 1
    k_gather<<<gather_blocks, 256>>>(data);
    k_gemm_tc<<<gemm_blocks, 256>>>(data, 0, b1, nullptr);

    // Layer 2
    k_gather<<<gather_blocks, 256>>>(nullptr);
    k_gemm_tc<<<gemm_blocks, 256>>>(nullptr, 256 * HD, b2, out);
}